// round 8
// baseline (speedup 1.0000x reference)
#include <cuda_runtime.h>

#define N_TRAJ  256
#define T_LEN   1024
#define K_TYPES 1000
#define D_EMB   64
#define EPS     1e-8f

#define N_ROWS      (N_TRAJ * T_LEN)                   // 262144
#define EMB_TOTAL   (N_ROWS * D_EMB)                   // 16777216
#define EMB_BULK4   ((EMB_TOTAL - 4) / 4)              // 4194303 quads at pos 3+4q
#define QPT         4                                  // quads per thread
#define QUADS_PER_BLOCK (256 * QPT)                    // 1024 quads = 64 rows
#define NBLOCKS     4096                               // 64 rows/block, exact
#define BLK_PER_TRAJ 16                                // 1024 / 64

__device__ int   g_reduce_ctr;             // zero-init; reset each launch
__device__ float g_part_ev[NBLOCKS];       // per-block partials (fixed slots)
__device__ float g_part_tm[NBLOCKS];

// ---------------------------------------------------------------------------
// One block = 64 output rows = 64 events (all in trajectory b/16).
//   1. stage 65 event indices in smem
//   2. threads 0-63 issue the random prob_event + intensities + mask loads
//      (DRAM latency starts ticking here)
//   3. emb path: QPT=4 quads/thread, 8 batched LDG.128 table reads, __stcs
//   4. consume gather results -> block partial (fixed order warp reduce)
//   5. last-arriving block folds 16 partials/trajectory (fixed order)
//      -> ll_N, time_loglik_NT, time_loglik
// ---------------------------------------------------------------------------
__global__ void fused_kernel(const int* __restrict__ event_types,
                             const float* __restrict__ prob_event,
                             const float* __restrict__ intensities,
                             const float* __restrict__ Lambda,
                             const float* __restrict__ input_mask,
                             const float* __restrict__ type_table,
                             float* __restrict__ out,
                             float* __restrict__ out_emb) {
    const int tid = threadIdx.x;
    const int b   = blockIdx.x;                        // 0 .. 4095

    // ---- stage the 65 event indices this block needs (rows 64b .. 64b+64) ----
    __shared__ int s_idx[65];
    if (tid < 65) {
        const int r = 64 * b + tid;
        s_idx[tid] = (r < N_ROWS) ? event_types[r] : 0;
    }
    __syncthreads();

    // ---- kick off the latency-critical gather loads (threads 0-63) ----
    float g_m = 0.0f, g_inz = 0.0f, g_p = 0.0f;
    if (tid < 64) {
        const int r = 64 * b + tid;                    // global event index
        g_m   = input_mask[r];
        g_inz = intensities[r];
        const int e = s_idx[tid];
        g_p = __ldcs(&prob_event[(long long)r * K_TYPES + e]);
    }

    // ---------------- embedding path (hides the gather latency) ----------------
    const int qbase = b * QUADS_PER_BLOCK + tid;

    int    pos[QPT];
    bool   ok[QPT];
    float4 lo[QPT], hi[QPT];

    #pragma unroll
    for (int k = 0; k < QPT; k++) {
        const int q = qbase + k * 256;
        ok[k]  = (q < EMB_BULK4);                  // only very last quad fails
        pos[k] = 3 + 4 * q;
        const int lrow = (pos[k] >> 6) - 64 * b;   // 0..63
        const int d    = pos[k] & (D_EMB - 1);     // 3,7,...,63

        const int e  = s_idx[lrow];
        const int eb = (d == D_EMB - 1) ? s_idx[lrow + 1] : e;
        const int o  = (d == D_EMB - 1) ? 0 : d + 1;

        if (ok[k]) {
            lo[k] = __ldg((const float4*)(type_table + e  * D_EMB + (d - 3)));
            hi[k] = __ldg((const float4*)(type_table + eb * D_EMB + o));
        }
    }

    #pragma unroll
    for (int k = 0; k < QPT; k++) {
        if (ok[k]) {
            float4 v;
            v.x = lo[k].w; v.y = hi[k].x; v.z = hi[k].y; v.w = hi[k].z;
            __stcs(reinterpret_cast<float4*>(out_emb + pos[k]), v);
        }
    }

    if (b == 0 && tid == 0) {
        // head pos 0,1,2 (row 0) and tail pos EMB_TOTAL-1
        const int eh = s_idx[0];
        out_emb[0] = __ldg(&type_table[eh * D_EMB + 0]);
        out_emb[1] = __ldg(&type_table[eh * D_EMB + 1]);
        out_emb[2] = __ldg(&type_table[eh * D_EMB + 2]);
        const int lrow = (EMB_TOTAL - 1) >> 6;
        const int el = __ldg(&event_types[lrow]);
        out_emb[EMB_TOTAL - 1] = __ldg(&type_table[el * D_EMB + (D_EMB - 1)]);
    }

    // ---------------- consume gather, block partial ----------------
    __shared__ float s_w_ev[2];
    __shared__ float s_w_tm[2];
    if (tid < 64) {
        float tm = __logf(g_inz + EPS) * g_m;
        float ev = __logf(g_p   + EPS) * g_m;
        // warp-level fixed-order reduction (tid 0-31 = warp 0, 32-63 = warp 1)
        #pragma unroll
        for (int s = 16; s > 0; s >>= 1) {
            tm += __shfl_down_sync(0xffffffffu, tm, s);
            ev += __shfl_down_sync(0xffffffffu, ev, s);
        }
        if ((tid & 31) == 0) {
            s_w_ev[tid >> 5] = ev;
            s_w_tm[tid >> 5] = tm;
        }
    }
    __syncthreads();
    if (tid == 0) {
        g_part_ev[b] = s_w_ev[0] + s_w_ev[1];
        g_part_tm[b] = s_w_tm[0] + s_w_tm[1];
    }

    // ---------------- deterministic fold in the last block ----------------
    __threadfence();                         // release partial writes
    __shared__ int is_last;
    if (tid == 0) {
        const int v = atomicAdd(&g_reduce_ctr, 1);
        is_last = (v == NBLOCKS - 1);
    }
    __syncthreads();
    if (is_last) {
        __threadfence();                     // acquire all partials
        // thread tid owns trajectory tid: partials 16*tid .. 16*tid+15
        float ev16 = 0.0f, tm16 = 0.0f;
        #pragma unroll
        for (int i = 0; i < BLK_PER_TRAJ; i++) {
            ev16 += g_part_ev[BLK_PER_TRAJ * tid + i];
            tm16 += g_part_tm[BLK_PER_TRAJ * tid + i];
        }
        const float tnt = tm16 - Lambda[tid];
        const float ll  = tnt + ev16;
        out[tid]              = ll;          // ll_N
        out[N_TRAJ + 1 + tid] = tnt;         // time_loglik_NT

        __shared__ float s_ll[256];
        s_ll[tid] = ll;
        __syncthreads();
        #pragma unroll
        for (int s = 128; s > 0; s >>= 1) {
            if (tid < s) s_ll[tid] += s_ll[tid + s];
            __syncthreads();
        }
        if (tid == 0) {
            out[N_TRAJ] = s_ll[0];           // time_loglik (scalar)
            g_reduce_ctr = 0;                // reset for graph replay
        }
    }
}

extern "C" void kernel_launch(void* const* d_in, const int* in_sizes, int n_in,
                              void* d_out, int out_size) {
    const int*   event_types = (const int*)  d_in[0];   // (N, T) int32
    const float* prob_event  = (const float*)d_in[1];   // (N, T, K)
    const float* intensities = (const float*)d_in[2];   // (N, T)
    const float* Lambda      = (const float*)d_in[3];   // (N,)
    const float* input_mask  = (const float*)d_in[4];   // (N, T)
    const float* type_table  = (const float*)d_in[5];   // (K, D)

    float* out = (float*)d_out;
    // Layout: [ll_N (256)] [time_loglik (1)] [time_loglik_NT (256)] [type_emb]
    float* out_emb = out + (N_TRAJ + 1 + N_TRAJ);

    fused_kernel<<<NBLOCKS, 256>>>(event_types, prob_event, intensities,
                                   Lambda, input_mask, type_table,
                                   out, out_emb);
}

// round 9
// speedup vs baseline: 1.4718x; 1.4718x over previous
#include <cuda_runtime.h>
#include <cstdint>

#define N_TRAJ  256
#define T_LEN   1024
#define K_TYPES 1000
#define D_EMB   64
#define EPS     1e-8f

#define N_ROWS      (N_TRAJ * T_LEN)                   // 262144
#define EMB_TOTAL   (N_ROWS * D_EMB)                   // 16777216
#define EMB_BULK4   ((EMB_TOTAL - 4) / 4)              // 4194303 quads at pos 3+4q
#define QPT         4                                  // quads per thread
#define QUADS_PER_BLOCK (256 * QPT)                    // 1024 quads = 64 rows
#define EMB_BLOCKS  4096                               // 64 rows per block, exact

__device__ int g_reduce_ctr;   // zero-init; reset at end of each launch

__device__ __forceinline__ uint32_t smem_u32(const void* p) {
    uint32_t a;
    asm("{ .reg .u64 t; cvta.to.shared.u64 t, %1; cvt.u32.u64 %0, t; }"
        : "=r"(a) : "l"(p));
    return a;
}

// ---------------------------------------------------------------------------
// Fused kernel:
//   blocks [0, 256)          : per-trajectory reduction (4 events/thread,
//                              batched gathers); last-done block folds the
//                              scalar sum deterministically.
//   blocks [256, 256+4096)   : embedding gather. Tile built in SMEM with the
//                              +3 rotation applied (STS.128, conflict-free),
//                              then ONE cp.async.bulk store per block — no
//                              per-thread STG.128 on the LSU pipe.
// ---------------------------------------------------------------------------
__global__ void fused_kernel(const int* __restrict__ event_types,
                             const float* __restrict__ prob_event,
                             const float* __restrict__ intensities,
                             const float* __restrict__ Lambda,
                             const float* __restrict__ input_mask,
                             const float* __restrict__ type_table,
                             float* __restrict__ out,
                             float* __restrict__ out_emb) {
    const int tid = threadIdx.x;

    if (blockIdx.x < N_TRAJ) {
        // ---------------- reduction path (R6 structure) ----------------
        const int n = blockIdx.x;
        const int base = n * T_LEN;

        float m[4], inz[4], p[4];
        #pragma unroll
        for (int i = 0; i < 4; i++) {
            const int t = base + tid + i * 256;
            m[i]   = input_mask[t];
            inz[i] = intensities[t];
            const int e = event_types[t];
            p[i] = __ldcs(&prob_event[(long long)t * K_TYPES + e]);
        }

        float ev = 0.0f, tm = 0.0f;
        #pragma unroll
        for (int i = 0; i < 4; i++) {
            tm = fmaf(__logf(inz[i] + EPS), m[i], tm);
            ev = fmaf(__logf(p[i]   + EPS), m[i], ev);
        }

        __shared__ float s_ev[256];
        __shared__ float s_tm[256];
        s_ev[tid] = ev;
        s_tm[tid] = tm;
        __syncthreads();

        #pragma unroll
        for (int s = 128; s > 0; s >>= 1) {
            if (tid < s) {
                s_ev[tid] += s_ev[tid + s];
                s_tm[tid] += s_tm[tid + s];
            }
            __syncthreads();
        }

        if (tid == 0) {
            const float tnt = s_tm[0] - Lambda[n];
            out[n]              = tnt + s_ev[0];   // ll_N
            out[N_TRAJ + 1 + n] = tnt;             // time_loglik_NT
        }

        __threadfence();
        __shared__ int is_last;
        if (tid == 0) {
            const int v = atomicAdd(&g_reduce_ctr, 1);
            is_last = (v == N_TRAJ - 1);
        }
        __syncthreads();
        if (is_last) {
            __threadfence();
            s_ev[tid] = out[tid];
            __syncthreads();
            #pragma unroll
            for (int s = 128; s > 0; s >>= 1) {
                if (tid < s) s_ev[tid] += s_ev[tid + s];
                __syncthreads();
            }
            if (tid == 0) {
                out[N_TRAJ] = s_ev[0];              // time_loglik
                g_reduce_ctr = 0;                   // reset for graph replay
            }
        }
        return;
    }

    // ---------------- embedding path ----------------
    const int b = blockIdx.x - N_TRAJ;                 // 0 .. 4095

    __shared__ int    s_idx[65];
    __shared__ float4 s_tile[1024];                    // 16 KB output-layout tile

    if (tid < 65) {
        const int r = 64 * b + tid;
        s_idx[tid] = (r < N_ROWS) ? event_types[r] : 0;
    }
    __syncthreads();

    // Phase 1: address math + issue all 8 independent LDG.128s (unconditional;
    // the one out-of-range quad in the last block reads s_idx[64]==0 -> safe).
    float4 lo[QPT], hi[QPT];
    #pragma unroll
    for (int k = 0; k < QPT; k++) {
        const int q   = b * QUADS_PER_BLOCK + tid + k * 256;
        const int pos = 3 + 4 * q;
        const int lrow = (pos >> 6) - 64 * b;          // 0..63
        const int d    = pos & (D_EMB - 1);            // 3,7,...,63

        const int e  = s_idx[lrow];
        const int eb = (d == D_EMB - 1) ? s_idx[lrow + 1] : e;
        const int o  = (d == D_EMB - 1) ? 0 : d + 1;

        lo[k] = __ldg((const float4*)(type_table + e  * D_EMB + (d - 3)));
        hi[k] = __ldg((const float4*)(type_table + eb * D_EMB + o));
    }

    // Phase 2: rotated recombine into the SMEM tile (STS.128, conflict-free).
    // Tile float j corresponds to emb pos 4096*b + 3 + j.
    #pragma unroll
    for (int k = 0; k < QPT; k++) {
        float4 v;
        v.x = lo[k].w; v.y = hi[k].x; v.z = hi[k].y; v.w = hi[k].z;
        s_tile[tid + 256 * k] = v;
    }
    __syncthreads();

    // Phase 3: one bulk async store SMEM -> GMEM per block.
    if (tid == 0) {
        asm volatile("fence.proxy.async.shared::cta;" ::: "memory");
        // last block: only 4092 valid floats (emb pos < EMB_TOTAL); the final
        // emb float (pos EMB_TOTAL-1) is written by the scalar tail below.
        const int bytes = (b == EMB_BLOCKS - 1) ? 4092 * 4 : 16384;
        float* gdst = out_emb + 3 + 4096 * b;          // 16B-aligned (513+3=516)
        const uint32_t saddr = smem_u32(s_tile);
        asm volatile("cp.async.bulk.global.shared::cta.bulk_group [%0], [%1], %2;"
                     :: "l"(gdst), "r"(saddr), "r"(bytes) : "memory");
        asm volatile("cp.async.bulk.commit_group;" ::: "memory");
        asm volatile("cp.async.bulk.wait_group 0;" ::: "memory");
    }

    if (b == 0 && tid == 1) {
        // head: emb pos 0,1,2 (row 0)
        const int eh = s_idx[0];
        out_emb[0] = __ldg(&type_table[eh * D_EMB + 0]);
        out_emb[1] = __ldg(&type_table[eh * D_EMB + 1]);
        out_emb[2] = __ldg(&type_table[eh * D_EMB + 2]);
    }
    if (b == EMB_BLOCKS - 1 && tid == 1) {
        // tail: emb pos EMB_TOTAL-1
        const int el = s_idx[63];                      // last row of last block
        out_emb[EMB_TOTAL - 1] = __ldg(&type_table[el * D_EMB + (D_EMB - 1)]);
    }
}

extern "C" void kernel_launch(void* const* d_in, const int* in_sizes, int n_in,
                              void* d_out, int out_size) {
    const int*   event_types = (const int*)  d_in[0];   // (N, T) int32
    const float* prob_event  = (const float*)d_in[1];   // (N, T, K)
    const float* intensities = (const float*)d_in[2];   // (N, T)
    const float* Lambda      = (const float*)d_in[3];   // (N,)
    const float* input_mask  = (const float*)d_in[4];   // (N, T)
    const float* type_table  = (const float*)d_in[5];   // (K, D)

    float* out = (float*)d_out;
    // Layout: [ll_N (256)] [time_loglik (1)] [time_loglik_NT (256)] [type_emb]
    float* out_emb = out + (N_TRAJ + 1 + N_TRAJ);

    fused_kernel<<<N_TRAJ + EMB_BLOCKS, 256>>>(event_types, prob_event,
                                               intensities, Lambda, input_mask,
                                               type_table, out, out_emb);
}